// round 1
// baseline (speedup 1.0000x reference)
#include <cuda_runtime.h>
#include <cuda_bf16.h>

#define N_NODES 100000
#define DIM 128
#define N_EDGES 1600000

// Scratch (allocation-free rule: device globals)
__device__ float  g_h[N_NODES * DIM];        // h = x @ W^T
__device__ float4 g_Wp[32 * 128];            // W repacked: g_Wp[k4*128 + o] = W[o][4k4..4k4+3]

// ---------------------------------------------------------------------------
// Repack W (128x128) so that for a fixed k4, the float4 chunks for consecutive
// output columns o are contiguous -> coalesced LDG.128 in the GEMM.
// ---------------------------------------------------------------------------
__global__ void k_prep_w(const float* __restrict__ W) {
    int idx = blockIdx.x * blockDim.x + threadIdx.x;   // 4096 total
    if (idx >= 32 * 128) return;
    int o  = idx & 127;
    int k4 = idx >> 7;
    const float4* W4 = reinterpret_cast<const float4*>(W);
    g_Wp[idx] = W4[o * 32 + k4];
}

// ---------------------------------------------------------------------------
// GEMM: h[n][o] = sum_k x[n][k] * W[o][k]
// Block = 128 threads (thread = output column o), 16 rows of x per block.
// x rows staged in shared; per k4: 1 coalesced LDG.128 of W + broadcast
// LDS.128 of x + 4 FMAs per row -> FFMA-bound.
// ---------------------------------------------------------------------------
__global__ void __launch_bounds__(128) k_gemm(const float* __restrict__ x) {
    __shared__ float4 sx[16 * 32];     // [r][k4]
    const int o    = threadIdx.x;      // 0..127
    const int row0 = blockIdx.x * 16;

    const float4* x4 = reinterpret_cast<const float4*>(x);
    // load 16 rows x 32 float4 = 512 float4, 4 per thread, fully coalesced
    #pragma unroll
    for (int i = o; i < 512; i += 128) {
        sx[i] = x4[row0 * 32 + i];
    }
    __syncthreads();

    float acc[16];
    #pragma unroll
    for (int r = 0; r < 16; r++) acc[r] = 0.0f;

    #pragma unroll 4
    for (int k4 = 0; k4 < 32; k4++) {
        float4 w = g_Wp[k4 * 128 + o];
        #pragma unroll
        for (int r = 0; r < 16; r++) {
            float4 xv = sx[r * 32 + k4];
            acc[r] += xv.x * w.x;
            acc[r] += xv.y * w.y;
            acc[r] += xv.z * w.z;
            acc[r] += xv.w * w.w;
        }
    }

    #pragma unroll
    for (int r = 0; r < 16; r++) {
        g_h[(row0 + r) * DIM + o] = acc[r];
    }
}

// ---------------------------------------------------------------------------
// Scatter: out[row[e]] += val[e] * h[col[e]]
// One warp per edge; each lane covers 4 columns (float4 gather + 4 REDG.F32).
// h and out both fit in L2 (51.2 MB each) -> L2-resident.
// ---------------------------------------------------------------------------
__global__ void __launch_bounds__(256) k_scatter(const int*   __restrict__ erow,
                                                 const int*   __restrict__ ecol,
                                                 const float* __restrict__ eval,
                                                 float*       __restrict__ out,
                                                 int n_edges) {
    int gtid = blockIdx.x * blockDim.x + threadIdx.x;
    int e    = gtid >> 5;
    int lane = threadIdx.x & 31;
    if (e >= n_edges) return;

    int   r = erow[e];   // warp-uniform (broadcast load)
    int   c = ecol[e];
    float v = eval[e];

    const float4* h4 = reinterpret_cast<const float4*>(g_h);
    float4 hv = h4[c * 32 + lane];

    float* op = out + r * DIM + lane * 4;
    atomicAdd(op + 0, hv.x * v);
    atomicAdd(op + 1, hv.y * v);
    atomicAdd(op + 2, hv.z * v);
    atomicAdd(op + 3, hv.w * v);
}

// ---------------------------------------------------------------------------
extern "C" void kernel_launch(void* const* d_in, const int* in_sizes, int n_in,
                              void* d_out, int out_size) {
    const float* x    = (const float*)d_in[0];   // [100000,128]
    const float* W    = (const float*)d_in[1];   // [128,128]
    const int*   erow = (const int*)  d_in[2];   // [1600000]
    const int*   ecol = (const int*)  d_in[3];
    const float* eval = (const float*)d_in[4];
    float*       out  = (float*)d_out;

    int n_nodes = in_sizes[0] / DIM;
    int n_edges = in_sizes[2];

    // 1) repack W
    k_prep_w<<<16, 256>>>(W);

    // 2) GEMM h = x @ W^T
    k_gemm<<<(n_nodes + 15) / 16, 128>>>(x);

    // 3) zero output (poisoned by harness)
    cudaMemsetAsync(d_out, 0, (size_t)out_size * sizeof(float));

    // 4) scatter-add
    int warps  = n_edges;                 // one warp per edge
    int blocks = (warps * 32 + 255) / 256;
    k_scatter<<<blocks, 256>>>(erow, ecol, eval, out, n_edges);
}

// round 2
// speedup vs baseline: 1.8699x; 1.8699x over previous
#include <cuda_runtime.h>
#include <cuda_bf16.h>

#define N_NODES 100000
#define DIM 128

// Scratch (allocation-free rule: device globals)
__device__ float g_h[N_NODES * DIM];   // h = x @ W^T
__device__ float g_Wt[DIM * DIM];      // Wt[k*128 + o] = W[o*128 + k]  (transposed)

// ---------------------------------------------------------------------------
// Transpose W so the GEMM reads W[k][o] contiguously in o (coalesced LDG.128,
// and the float4 gives two f32x2 multiplier pairs for adjacent outputs).
// ---------------------------------------------------------------------------
__global__ void k_prep_w(const float* __restrict__ W) {
    int idx = blockIdx.x * blockDim.x + threadIdx.x;   // 16384
    if (idx >= DIM * DIM) return;
    int o = idx & 127;
    int k = idx >> 7;
    g_Wt[idx] = W[o * DIM + k];
}

// ---------------------------------------------------------------------------
// packed fp32x2 FMA: d = a*b + d (per 32-bit half). PTX-only on sm_103a.
// ---------------------------------------------------------------------------
__device__ __forceinline__ void ffma2(float2& d, float2 a, float2 b) {
    asm("fma.rn.f32x2 %0, %1, %2, %0;"
        : "+l"(*reinterpret_cast<unsigned long long*>(&d))
        : "l"(*reinterpret_cast<unsigned long long*>(&a)),
          "l"(*reinterpret_cast<unsigned long long*>(&b)));
}

// ---------------------------------------------------------------------------
// GEMM: h[n][o] = sum_k x[n][k] * W[o][k], fp32x2 packed over output pairs.
// Block = 128 threads, 32 rows per block.
//   thread: op = tid&31  -> outputs [4op .. 4op+3] (two f32x2 pairs)
//           rg = tid>>5  -> rows   [8rg .. 8rg+7]
// x staged in shared PRE-DUPLICATED as {x,x} so LDS.64 feeds FFMA2 directly
// (no per-FMA pack ALU op). All lanes of a warp read the same sxd address
// -> broadcast, conflict-free.
// ---------------------------------------------------------------------------
__global__ void __launch_bounds__(128) k_gemm(const float* __restrict__ x) {
    __shared__ float2 sxd[32 * DIM];   // 32 KB, [row][k] duplicated
    const int tid  = threadIdx.x;
    const int op   = tid & 31;
    const int rg   = tid >> 5;
    const int row0 = blockIdx.x * 32;

    // Stage 32 rows (1024 float4 loads, coalesced), store duplicated.
    const float4* x4 = reinterpret_cast<const float4*>(x + (size_t)row0 * DIM);
    #pragma unroll
    for (int i = tid; i < 32 * 32; i += 128) {
        float4 v  = x4[i];
        int    r  = i >> 5;
        int    k4 = i & 31;
        float2* d = &sxd[r * DIM + k4 * 4];
        d[0] = make_float2(v.x, v.x);
        d[1] = make_float2(v.y, v.y);
        d[2] = make_float2(v.z, v.z);
        d[3] = make_float2(v.w, v.w);
    }
    __syncthreads();

    float2 acc[8][2];
    #pragma unroll
    for (int r = 0; r < 8; r++) {
        acc[r][0] = make_float2(0.f, 0.f);
        acc[r][1] = make_float2(0.f, 0.f);
    }

    const float2* sxr = &sxd[(rg * 8) * DIM];

    #pragma unroll 2
    for (int k = 0; k < DIM; k++) {
        float4 wv = *reinterpret_cast<const float4*>(&g_Wt[k * DIM + op * 4]);
        float2 wa = make_float2(wv.x, wv.y);
        float2 wb = make_float2(wv.z, wv.w);
        #pragma unroll
        for (int r = 0; r < 8; r++) {
            float2 xv = sxr[r * DIM + k];
            ffma2(acc[r][0], wa, xv);
            ffma2(acc[r][1], wb, xv);
        }
    }

    // Epilogue: STG.128 per row, coalesced across the warp.
    float* hp = g_h + (size_t)(row0 + rg * 8) * DIM + op * 4;
    #pragma unroll
    for (int r = 0; r < 8; r++) {
        float4 o4 = make_float4(acc[r][0].x, acc[r][0].y, acc[r][1].x, acc[r][1].y);
        *reinterpret_cast<float4*>(hp + (size_t)r * DIM) = o4;
    }
}

// ---------------------------------------------------------------------------
// Scatter: out[row[e]] += val[e] * h[col[e]]
// One warp per edge; lane covers 4 columns. Single red.global.add.v4.f32
// per lane (1 instruction / 16B) instead of 4 scalar REDs.
// ---------------------------------------------------------------------------
__global__ void __launch_bounds__(256) k_scatter(const int*   __restrict__ erow,
                                                 const int*   __restrict__ ecol,
                                                 const float* __restrict__ eval,
                                                 float*       __restrict__ out,
                                                 int n_edges) {
    int gtid = blockIdx.x * blockDim.x + threadIdx.x;
    int e    = gtid >> 5;
    int lane = threadIdx.x & 31;
    if (e >= n_edges) return;

    int   r = __ldg(erow + e);   // warp-uniform
    int   c = __ldg(ecol + e);
    float v = __ldg(eval + e);

    const float4* h4 = reinterpret_cast<const float4*>(g_h);
    float4 hv = h4[(size_t)c * 32 + lane];

    float* op = out + (size_t)r * DIM + lane * 4;
    asm volatile("red.global.add.v4.f32 [%0], {%1,%2,%3,%4};"
                 :: "l"(op), "f"(hv.x * v), "f"(hv.y * v),
                    "f"(hv.z * v), "f"(hv.w * v)
                 : "memory");
}

// ---------------------------------------------------------------------------
extern "C" void kernel_launch(void* const* d_in, const int* in_sizes, int n_in,
                              void* d_out, int out_size) {
    const float* x    = (const float*)d_in[0];   // [100000,128]
    const float* W    = (const float*)d_in[1];   // [128,128]
    const int*   erow = (const int*)  d_in[2];   // [1600000]
    const int*   ecol = (const int*)  d_in[3];
    const float* eval = (const float*)d_in[4];
    float*       out  = (float*)d_out;

    int n_nodes = in_sizes[0] / DIM;
    int n_edges = in_sizes[2];

    // 1) transpose W
    k_prep_w<<<(DIM * DIM + 255) / 256, 256>>>(W);

    // 2) GEMM h = x @ W^T  (32 rows/block; 100000 = 32 * 3125 exactly)
    k_gemm<<<(n_nodes + 31) / 32, 128>>>(x);

    // 3) zero output (poisoned by harness)
    cudaMemsetAsync(d_out, 0, (size_t)out_size * sizeof(float));

    // 4) scatter-add
    int blocks = (int)(((long long)n_edges * 32 + 255) / 256);
    k_scatter<<<blocks, 256>>>(erow, ecol, eval, out, n_edges);
}

// round 4
// speedup vs baseline: 2.6561x; 1.4205x over previous
#include <cuda_runtime.h>
#include <cuda_bf16.h>

#define N_NODES 100000
#define DIM 128
#define MAX_EDGES 1700000
#define SCAN_CHUNK 512
#define N_CHUNKS ((N_NODES + SCAN_CHUNK - 1) / SCAN_CHUNK)   // 196

// ---------------------------------------------------------------------------
// Scratch (allocation-free rule: device globals)
// ---------------------------------------------------------------------------
__device__ float g_h[N_NODES * DIM];          // h = x @ W^T
__device__ float g_Wt[DIM * DIM];             // transposed W
__device__ int   g_cnt[N_NODES];              // per-row edge count (then chunk-scanned)
__device__ int   g_rowstart[N_NODES + 1];     // CSR offsets
__device__ int   g_cursor[N_NODES];           // placement cursors
__device__ int   g_blocksum[N_CHUNKS];        // scan partials
__device__ int2  g_edge[MAX_EDGES];           // (col, val-bits) grouped by row

// ---------------------------------------------------------------------------
__global__ void k_prep_w(const float* __restrict__ W) {
    int idx = blockIdx.x * blockDim.x + threadIdx.x;
    if (idx >= DIM * DIM) return;
    int o = idx & 127;
    int k = idx >> 7;
    g_Wt[idx] = W[o * DIM + k];
}

// ---------------------------------------------------------------------------
// packed fp32x2 FMA (PTX-only on sm_103a)
// ---------------------------------------------------------------------------
__device__ __forceinline__ void ffma2(float2& d, float2 a, float2 b) {
    asm("fma.rn.f32x2 %0, %1, %2, %0;"
        : "+l"(*reinterpret_cast<unsigned long long*>(&d))
        : "l"(*reinterpret_cast<unsigned long long*>(&a)),
          "l"(*reinterpret_cast<unsigned long long*>(&b)));
}

// ---------------------------------------------------------------------------
// GEMM: h = x @ W^T  (unchanged from round 2 — proven ~2x over scalar FFMA)
// ---------------------------------------------------------------------------
__global__ void __launch_bounds__(128) k_gemm(const float* __restrict__ x) {
    __shared__ float2 sxd[32 * DIM];
    const int tid  = threadIdx.x;
    const int op   = tid & 31;
    const int rg   = tid >> 5;
    const int row0 = blockIdx.x * 32;

    const float4* x4 = reinterpret_cast<const float4*>(x + (size_t)row0 * DIM);
    #pragma unroll
    for (int i = tid; i < 32 * 32; i += 128) {
        float4 v  = x4[i];
        int    r  = i >> 5;
        int    k4 = i & 31;
        float2* d = &sxd[r * DIM + k4 * 4];
        d[0] = make_float2(v.x, v.x);
        d[1] = make_float2(v.y, v.y);
        d[2] = make_float2(v.z, v.z);
        d[3] = make_float2(v.w, v.w);
    }
    __syncthreads();

    float2 acc[8][2];
    #pragma unroll
    for (int r = 0; r < 8; r++) {
        acc[r][0] = make_float2(0.f, 0.f);
        acc[r][1] = make_float2(0.f, 0.f);
    }

    const float2* sxr = &sxd[(rg * 8) * DIM];

    #pragma unroll 2
    for (int k = 0; k < DIM; k++) {
        float4 wv = *reinterpret_cast<const float4*>(&g_Wt[k * DIM + op * 4]);
        float2 wa = make_float2(wv.x, wv.y);
        float2 wb = make_float2(wv.z, wv.w);
        #pragma unroll
        for (int r = 0; r < 8; r++) {
            float2 xv = sxr[r * DIM + k];
            ffma2(acc[r][0], wa, xv);
            ffma2(acc[r][1], wb, xv);
        }
    }

    float* hp = g_h + (size_t)(row0 + rg * 8) * DIM + op * 4;
    #pragma unroll
    for (int r = 0; r < 8; r++) {
        float4 o4 = make_float4(acc[r][0].x, acc[r][0].y, acc[r][1].x, acc[r][1].y);
        *reinterpret_cast<float4*>(hp + (size_t)r * DIM) = o4;
    }
}

// ---------------------------------------------------------------------------
// Binning phase 0: zero counts (device global persists across replays!)
// ---------------------------------------------------------------------------
__global__ void k_zero_cnt() {
    int i = blockIdx.x * blockDim.x + threadIdx.x;
    if (i < N_NODES) g_cnt[i] = 0;
}

// Phase 1: histogram of rows
__global__ void k_hist(const int* __restrict__ erow, int n_edges) {
    int e = blockIdx.x * blockDim.x + threadIdx.x;
    if (e < n_edges) atomicAdd(&g_cnt[erow[e]], 1);
}

// ---------------------------------------------------------------------------
// Phase 2a: per-chunk exclusive scan (chunk = 512), store chunk totals.
// g_cnt[i] is replaced by its exclusive-scan-within-chunk value.
// ---------------------------------------------------------------------------
__global__ void __launch_bounds__(SCAN_CHUNK) k_scan1() {
    __shared__ int wsum[SCAN_CHUNK / 32];
    int tid  = threadIdx.x;
    int gidx = blockIdx.x * SCAN_CHUNK + tid;
    int v    = (gidx < N_NODES) ? g_cnt[gidx] : 0;

    int lane = tid & 31, wid = tid >> 5;
    // warp inclusive scan
    int incl = v;
    #pragma unroll
    for (int d = 1; d < 32; d <<= 1) {
        int t = __shfl_up_sync(0xffffffff, incl, d);
        if (lane >= d) incl += t;
    }
    if (lane == 31) wsum[wid] = incl;
    __syncthreads();
    if (wid == 0) {
        int w = (lane < SCAN_CHUNK / 32) ? wsum[lane] : 0;
        int wi = w;
        #pragma unroll
        for (int d = 1; d < 32; d <<= 1) {
            int t = __shfl_up_sync(0xffffffff, wi, d);
            if (lane >= d) wi += t;
        }
        if (lane < SCAN_CHUNK / 32) wsum[lane] = wi - w;   // exclusive
    }
    __syncthreads();
    int excl = incl - v + wsum[wid];
    if (gidx < N_NODES) g_cnt[gidx] = excl;
    if (tid == SCAN_CHUNK - 1) g_blocksum[blockIdx.x] = excl + v;
}

// Phase 2b: single-block exclusive scan of chunk totals (N_CHUNKS = 196)
__global__ void __launch_bounds__(256) k_scan2() {
    __shared__ int wsum[8];
    int tid = threadIdx.x;
    int v   = (tid < N_CHUNKS) ? g_blocksum[tid] : 0;
    int lane = tid & 31, wid = tid >> 5;
    int incl = v;
    #pragma unroll
    for (int d = 1; d < 32; d <<= 1) {
        int t = __shfl_up_sync(0xffffffff, incl, d);
        if (lane >= d) incl += t;
    }
    if (lane == 31) wsum[wid] = incl;
    __syncthreads();
    if (wid == 0) {
        int w = (lane < 8) ? wsum[lane] : 0;
        int wi = w;
        #pragma unroll
        for (int d = 1; d < 32; d <<= 1) {
            int t = __shfl_up_sync(0xffffffff, wi, d);
            if (lane >= d) wi += t;
        }
        if (lane < 8) wsum[lane] = wi - w;
    }
    __syncthreads();
    if (tid < N_CHUNKS) g_blocksum[tid] = incl - v + wsum[wid];
}

// Phase 2c: combine -> rowstart, init cursor
__global__ void k_scan3(int n_edges) {
    int i = blockIdx.x * blockDim.x + threadIdx.x;
    if (i < N_NODES) {
        int rs = g_cnt[i] + g_blocksum[i / SCAN_CHUNK];
        g_rowstart[i] = rs;
        g_cursor[i]   = rs;
    }
    if (i == 0) g_rowstart[N_NODES] = n_edges;
}

// Phase 3: place (col,val) grouped by row
__global__ void k_place(const int*   __restrict__ erow,
                        const int*   __restrict__ ecol,
                        const float* __restrict__ eval,
                        int n_edges) {
    int e = blockIdx.x * blockDim.x + threadIdx.x;
    if (e >= n_edges) return;
    int r   = erow[e];
    int pos = atomicAdd(&g_cursor[r], 1);
    g_edge[pos] = make_int2(ecol[e], __float_as_int(eval[e]));
}

// ---------------------------------------------------------------------------
// Phase 4: one warp per output row; accumulate in registers, single
// coalesced non-atomic store. 4 interleaved chains for MLP=4.
// ---------------------------------------------------------------------------
__global__ void __launch_bounds__(256) k_rowgather(float* __restrict__ out) {
    int warp = blockIdx.x * 8 + (threadIdx.x >> 5);
    int lane = threadIdx.x & 31;
    if (warp >= N_NODES) return;

    int beg = g_rowstart[warp];
    int end = g_rowstart[warp + 1];

    const float4* h4 = reinterpret_cast<const float4*>(g_h);

    float4 a0 = make_float4(0.f, 0.f, 0.f, 0.f);
    float4 a1 = make_float4(0.f, 0.f, 0.f, 0.f);
    float4 a2 = make_float4(0.f, 0.f, 0.f, 0.f);
    float4 a3 = make_float4(0.f, 0.f, 0.f, 0.f);

    int i = beg;
    for (; i + 4 <= end; i += 4) {
        int2 e0 = g_edge[i + 0];
        int2 e1 = g_edge[i + 1];
        int2 e2 = g_edge[i + 2];
        int2 e3 = g_edge[i + 3];
        float4 h0 = h4[(size_t)e0.x * 32 + lane];
        float4 h1 = h4[(size_t)e1.x * 32 + lane];
        float4 h2 = h4[(size_t)e2.x * 32 + lane];
        float4 h3 = h4[(size_t)e3.x * 32 + lane];
        float v0 = __int_as_float(e0.y);
        float v1 = __int_as_float(e1.y);
        float v2 = __int_as_float(e2.y);
        float v3 = __int_as_float(e3.y);
        a0.x += v0 * h0.x; a0.y += v0 * h0.y; a0.z += v0 * h0.z; a0.w += v0 * h0.w;
        a1.x += v1 * h1.x; a1.y += v1 * h1.y; a1.z += v1 * h1.z; a1.w += v1 * h1.w;
        a2.x += v2 * h2.x; a2.y += v2 * h2.y; a2.z += v2 * h2.z; a2.w += v2 * h2.w;
        a3.x += v3 * h3.x; a3.y += v3 * h3.y; a3.z += v3 * h3.z; a3.w += v3 * h3.w;
    }
    for (; i < end; i++) {
        int2 e0 = g_edge[i];
        float4 h0 = h4[(size_t)e0.x * 32 + lane];
        float v0 = __int_as_float(e0.y);
        a0.x += v0 * h0.x; a0.y += v0 * h0.y; a0.z += v0 * h0.z; a0.w += v0 * h0.w;
    }

    float4 acc = make_float4(a0.x + a1.x + a2.x + a3.x,
                             a0.y + a1.y + a2.y + a3.y,
                             a0.z + a1.z + a2.z + a3.z,
                             a0.w + a1.w + a2.w + a3.w);
    *reinterpret_cast<float4*>(out + (size_t)warp * DIM + lane * 4) = acc;
}

// ---------------------------------------------------------------------------
extern "C" void kernel_launch(void* const* d_in, const int* in_sizes, int n_in,
                              void* d_out, int out_size) {
    const float* x    = (const float*)d_in[0];
    const float* W    = (const float*)d_in[1];
    const int*   erow = (const int*)  d_in[2];
    const int*   ecol = (const int*)  d_in[3];
    const float* eval = (const float*)d_in[4];
    float*       out  = (float*)d_out;

    int n_nodes = in_sizes[0] / DIM;
    int n_edges = in_sizes[2];

    // GEMM path
    k_prep_w<<<(DIM * DIM + 255) / 256, 256>>>(W);
    k_gemm<<<(n_nodes + 31) / 32, 128>>>(x);

    // Binning path (independent of GEMM, serialized on stream)
    k_zero_cnt<<<(N_NODES + 255) / 256, 256>>>();
    k_hist<<<(n_edges + 255) / 256, 256>>>(erow, n_edges);
    k_scan1<<<N_CHUNKS, SCAN_CHUNK>>>();
    k_scan2<<<1, 256>>>();
    k_scan3<<<(N_NODES + 255) / 256, 256>>>(n_edges);
    k_place<<<(n_edges + 255) / 256, 256>>>(erow, ecol, eval, n_edges);

    // Gather-accumulate (writes every output row -> no memset needed)
    k_rowgather<<<(N_NODES + 7) / 8, 256>>>(out);
}

// round 5
// speedup vs baseline: 2.8599x; 1.0767x over previous
#include <cuda_runtime.h>
#include <cuda_bf16.h>

#define N_NODES 100000
#define DIM 128
#define MAX_EDGES 1700000
#define SCAN_CHUNK 512
#define N_CHUNKS ((N_NODES + SCAN_CHUNK - 1) / SCAN_CHUNK)   // 196

// ---------------------------------------------------------------------------
// Scratch (allocation-free rule: device globals)
// ---------------------------------------------------------------------------
__device__ float g_h[N_NODES * DIM];          // h = x @ W^T
__device__ float g_Wt[DIM * DIM];             // transposed W
__device__ int   g_cnt[N_NODES];              // per-row edge count (then chunk-scanned)
__device__ int   g_rowstart[N_NODES + 1];     // CSR offsets
__device__ int   g_cursor[N_NODES];           // placement cursors
__device__ int   g_blocksum[N_CHUNKS];        // scan partials
__device__ int2  g_edge[MAX_EDGES];           // (col, val-bits) grouped by row

// ---------------------------------------------------------------------------
__global__ void k_prep_w(const float* __restrict__ W) {
    int idx = blockIdx.x * blockDim.x + threadIdx.x;
    if (idx >= DIM * DIM) return;
    int o = idx & 127;
    int k = idx >> 7;
    g_Wt[idx] = W[o * DIM + k];
}

// ---------------------------------------------------------------------------
// packed fp32x2 FMA (PTX-only on sm_103a)
// ---------------------------------------------------------------------------
__device__ __forceinline__ void ffma2(float2& d, float2 a, float2 b) {
    asm("fma.rn.f32x2 %0, %1, %2, %0;"
        : "+l"(*reinterpret_cast<unsigned long long*>(&d))
        : "l"(*reinterpret_cast<unsigned long long*>(&a)),
          "l"(*reinterpret_cast<unsigned long long*>(&b)));
}

// ---------------------------------------------------------------------------
// GEMM: h = x @ W^T  (unchanged — proven)
// ---------------------------------------------------------------------------
__global__ void __launch_bounds__(128) k_gemm(const float* __restrict__ x) {
    __shared__ float2 sxd[32 * DIM];
    const int tid  = threadIdx.x;
    const int op   = tid & 31;
    const int rg   = tid >> 5;
    const int row0 = blockIdx.x * 32;

    const float4* x4 = reinterpret_cast<const float4*>(x + (size_t)row0 * DIM);
    #pragma unroll
    for (int i = tid; i < 32 * 32; i += 128) {
        float4 v  = x4[i];
        int    r  = i >> 5;
        int    k4 = i & 31;
        float2* d = &sxd[r * DIM + k4 * 4];
        d[0] = make_float2(v.x, v.x);
        d[1] = make_float2(v.y, v.y);
        d[2] = make_float2(v.z, v.z);
        d[3] = make_float2(v.w, v.w);
    }
    __syncthreads();

    float2 acc[8][2];
    #pragma unroll
    for (int r = 0; r < 8; r++) {
        acc[r][0] = make_float2(0.f, 0.f);
        acc[r][1] = make_float2(0.f, 0.f);
    }

    const float2* sxr = &sxd[(rg * 8) * DIM];

    #pragma unroll 2
    for (int k = 0; k < DIM; k++) {
        float4 wv = *reinterpret_cast<const float4*>(&g_Wt[k * DIM + op * 4]);
        float2 wa = make_float2(wv.x, wv.y);
        float2 wb = make_float2(wv.z, wv.w);
        #pragma unroll
        for (int r = 0; r < 8; r++) {
            float2 xv = sxr[r * DIM + k];
            ffma2(acc[r][0], wa, xv);
            ffma2(acc[r][1], wb, xv);
        }
    }

    float* hp = g_h + (size_t)(row0 + rg * 8) * DIM + op * 4;
    #pragma unroll
    for (int r = 0; r < 8; r++) {
        float4 o4 = make_float4(acc[r][0].x, acc[r][0].y, acc[r][1].x, acc[r][1].y);
        *reinterpret_cast<float4*>(hp + (size_t)r * DIM) = o4;
    }
}

// ---------------------------------------------------------------------------
__global__ void k_zero_cnt() {
    int i = blockIdx.x * blockDim.x + threadIdx.x;
    if (i < N_NODES) g_cnt[i] = 0;
}

// Phase 1: histogram of rows — int4 loads, 4 edges per thread
__global__ void k_hist(const int* __restrict__ erow, int n_edges) {
    int t  = blockIdx.x * blockDim.x + threadIdx.x;
    int e4 = n_edges >> 2;
    if (t < e4) {
        int4 r = reinterpret_cast<const int4*>(erow)[t];
        atomicAdd(&g_cnt[r.x], 1);
        atomicAdd(&g_cnt[r.y], 1);
        atomicAdd(&g_cnt[r.z], 1);
        atomicAdd(&g_cnt[r.w], 1);
    } else {
        int e = e4 * 4 + (t - e4);
        if (e < n_edges) atomicAdd(&g_cnt[erow[e]], 1);
    }
}

// ---------------------------------------------------------------------------
// Phase 2a: per-chunk exclusive scan (chunk = 512), store chunk totals.
// ---------------------------------------------------------------------------
__global__ void __launch_bounds__(SCAN_CHUNK) k_scan1() {
    __shared__ int wsum[SCAN_CHUNK / 32];
    int tid  = threadIdx.x;
    int gidx = blockIdx.x * SCAN_CHUNK + tid;
    int v    = (gidx < N_NODES) ? g_cnt[gidx] : 0;

    int lane = tid & 31, wid = tid >> 5;
    int incl = v;
    #pragma unroll
    for (int d = 1; d < 32; d <<= 1) {
        int t = __shfl_up_sync(0xffffffff, incl, d);
        if (lane >= d) incl += t;
    }
    if (lane == 31) wsum[wid] = incl;
    __syncthreads();
    if (wid == 0) {
        int w = (lane < SCAN_CHUNK / 32) ? wsum[lane] : 0;
        int wi = w;
        #pragma unroll
        for (int d = 1; d < 32; d <<= 1) {
            int t = __shfl_up_sync(0xffffffff, wi, d);
            if (lane >= d) wi += t;
        }
        if (lane < SCAN_CHUNK / 32) wsum[lane] = wi - w;
    }
    __syncthreads();
    int excl = incl - v + wsum[wid];
    if (gidx < N_NODES) g_cnt[gidx] = excl;
    if (tid == SCAN_CHUNK - 1) g_blocksum[blockIdx.x] = excl + v;
}

// Phase 2b: single-block exclusive scan of chunk totals
__global__ void __launch_bounds__(256) k_scan2() {
    __shared__ int wsum[8];
    int tid = threadIdx.x;
    int v   = (tid < N_CHUNKS) ? g_blocksum[tid] : 0;
    int lane = tid & 31, wid = tid >> 5;
    int incl = v;
    #pragma unroll
    for (int d = 1; d < 32; d <<= 1) {
        int t = __shfl_up_sync(0xffffffff, incl, d);
        if (lane >= d) incl += t;
    }
    if (lane == 31) wsum[wid] = incl;
    __syncthreads();
    if (wid == 0) {
        int w = (lane < 8) ? wsum[lane] : 0;
        int wi = w;
        #pragma unroll
        for (int d = 1; d < 32; d <<= 1) {
            int t = __shfl_up_sync(0xffffffff, wi, d);
            if (lane >= d) wi += t;
        }
        if (lane < 8) wsum[lane] = wi - w;
    }
    __syncthreads();
    if (tid < N_CHUNKS) g_blocksum[tid] = incl - v + wsum[wid];
}

// Phase 2c: combine -> rowstart, init cursor
__global__ void k_scan3(int n_edges) {
    int i = blockIdx.x * blockDim.x + threadIdx.x;
    if (i < N_NODES) {
        int rs = g_cnt[i] + g_blocksum[i / SCAN_CHUNK];
        g_rowstart[i] = rs;
        g_cursor[i]   = rs;
    }
    if (i == 0) g_rowstart[N_NODES] = n_edges;
}

// Phase 3: place (col,val) grouped by row
__global__ void k_place(const int*   __restrict__ erow,
                        const int*   __restrict__ ecol,
                        const float* __restrict__ eval,
                        int n_edges) {
    int e = blockIdx.x * blockDim.x + threadIdx.x;
    if (e >= n_edges) return;
    int r   = erow[e];
    int pos = atomicAdd(&g_cursor[r], 1);
    g_edge[pos] = make_int2(ecol[e], __float_as_int(eval[e]));
}

// ---------------------------------------------------------------------------
// Phase 4: one warp per output row; 8 gather loads in flight (MLP=8),
// 128-thread blocks for tail balance. Single coalesced non-atomic store.
// ---------------------------------------------------------------------------
__global__ void __launch_bounds__(128) k_rowgather(float* __restrict__ out) {
    int warp = blockIdx.x * 4 + (threadIdx.x >> 5);
    int lane = threadIdx.x & 31;
    if (warp >= N_NODES) return;

    int beg = __ldg(&g_rowstart[warp]);
    int end = __ldg(&g_rowstart[warp + 1]);

    const float4* h4 = reinterpret_cast<const float4*>(g_h);

    float4 a0 = make_float4(0.f, 0.f, 0.f, 0.f);
    float4 a1 = make_float4(0.f, 0.f, 0.f, 0.f);
    float4 a2 = make_float4(0.f, 0.f, 0.f, 0.f);
    float4 a3 = make_float4(0.f, 0.f, 0.f, 0.f);

    int i = beg;
    // 8-deep batches: 8 independent L2 gathers in flight
    for (; i + 8 <= end; i += 8) {
        int2 e0 = g_edge[i + 0];
        int2 e1 = g_edge[i + 1];
        int2 e2 = g_edge[i + 2];
        int2 e3 = g_edge[i + 3];
        int2 e4 = g_edge[i + 4];
        int2 e5 = g_edge[i + 5];
        int2 e6 = g_edge[i + 6];
        int2 e7 = g_edge[i + 7];
        float4 h0 = h4[(size_t)e0.x * 32 + lane];
        float4 h1 = h4[(size_t)e1.x * 32 + lane];
        float4 h2 = h4[(size_t)e2.x * 32 + lane];
        float4 h3 = h4[(size_t)e3.x * 32 + lane];
        float4 h5 = h4[(size_t)e5.x * 32 + lane];
        float4 h6 = h4[(size_t)e6.x * 32 + lane];
        float4 h7 = h4[(size_t)e7.x * 32 + lane];
        float4 h4v = h4[(size_t)e4.x * 32 + lane];
        float v0 = __int_as_float(e0.y), v1 = __int_as_float(e1.y);
        float v2 = __int_as_float(e2.y), v3 = __int_as_float(e3.y);
        float v4 = __int_as_float(e4.y), v5 = __int_as_float(e5.y);
        float v6 = __int_as_float(e6.y), v7 = __int_as_float(e7.y);
        a0.x += v0 * h0.x; a0.y += v0 * h0.y; a0.z += v0 * h0.z; a0.w += v0 * h0.w;
        a1.x += v1 * h1.x; a1.y += v1 * h1.y; a1.z += v1 * h1.z; a1.w += v1 * h1.w;
        a2.x += v2 * h2.x; a2.y += v2 * h2.y; a2.z += v2 * h2.z; a2.w += v2 * h2.w;
        a3.x += v3 * h3.x; a3.y += v3 * h3.y; a3.z += v3 * h3.z; a3.w += v3 * h3.w;
        a0.x += v4 * h4v.x; a0.y += v4 * h4v.y; a0.z += v4 * h4v.z; a0.w += v4 * h4v.w;
        a1.x += v5 * h5.x; a1.y += v5 * h5.y; a1.z += v5 * h5.z; a1.w += v5 * h5.w;
        a2.x += v6 * h6.x; a2.y += v6 * h6.y; a2.z += v6 * h6.z; a2.w += v6 * h6.w;
        a3.x += v7 * h7.x; a3.y += v7 * h7.y; a3.z += v7 * h7.z; a3.w += v7 * h7.w;
    }
    // 4-deep
    for (; i + 4 <= end; i += 4) {
        int2 e0 = g_edge[i + 0];
        int2 e1 = g_edge[i + 1];
        int2 e2 = g_edge[i + 2];
        int2 e3 = g_edge[i + 3];
        float4 h0 = h4[(size_t)e0.x * 32 + lane];
        float4 h1 = h4[(size_t)e1.x * 32 + lane];
        float4 h2 = h4[(size_t)e2.x * 32 + lane];
        float4 h3 = h4[(size_t)e3.x * 32 + lane];
        float v0 = __int_as_float(e0.y), v1 = __int_as_float(e1.y);
        float v2 = __int_as_float(e2.y), v3 = __int_as_float(e3.y);
        a0.x += v0 * h0.x; a0.y += v0 * h0.y; a0.z += v0 * h0.z; a0.w += v0 * h0.w;
        a1.x += v1 * h1.x; a1.y += v1 * h1.y; a1.z += v1 * h1.z; a1.w += v1 * h1.w;
        a2.x += v2 * h2.x; a2.y += v2 * h2.y; a2.z += v2 * h2.z; a2.w += v2 * h2.w;
        a3.x += v3 * h3.x; a3.y += v3 * h3.y; a3.z += v3 * h3.z; a3.w += v3 * h3.w;
    }
    for (; i < end; i++) {
        int2 e0 = g_edge[i];
        float4 h0 = h4[(size_t)e0.x * 32 + lane];
        float v0 = __int_as_float(e0.y);
        a0.x += v0 * h0.x; a0.y += v0 * h0.y; a0.z += v0 * h0.z; a0.w += v0 * h0.w;
    }

    float4 acc = make_float4(a0.x + a1.x + a2.x + a3.x,
                             a0.y + a1.y + a2.y + a3.y,
                             a0.z + a1.z + a2.z + a3.z,
                             a0.w + a1.w + a2.w + a3.w);
    *reinterpret_cast<float4*>(out + (size_t)warp * DIM + lane * 4) = acc;
}

// ---------------------------------------------------------------------------
extern "C" void kernel_launch(void* const* d_in, const int* in_sizes, int n_in,
                              void* d_out, int out_size) {
    const float* x    = (const float*)d_in[0];
    const float* W    = (const float*)d_in[1];
    const int*   erow = (const int*)  d_in[2];
    const int*   ecol = (const int*)  d_in[3];
    const float* eval = (const float*)d_in[4];
    float*       out  = (float*)d_out;

    int n_nodes = in_sizes[0] / DIM;
    int n_edges = in_sizes[2];

    // Lazily create side stream + events on the first (non-capture) call.
    // During graph capture these already exist; event record/wait become
    // fork/join edges -> GEMM branch runs parallel to the binning branch.
    static cudaStream_t s2 = nullptr;
    static cudaEvent_t  ev_fork = nullptr, ev_join = nullptr;
    if (!s2) {
        cudaStreamCreate(&s2);
        cudaEventCreateWithFlags(&ev_fork, cudaEventDisableTiming);
        cudaEventCreateWithFlags(&ev_join, cudaEventDisableTiming);
    }

    // Fork: GEMM path on s2
    cudaEventRecord(ev_fork, 0);
    cudaStreamWaitEvent(s2, ev_fork, 0);
    k_prep_w<<<(DIM * DIM + 255) / 256, 256, 0, s2>>>(W);
    k_gemm<<<(n_nodes + 31) / 32, 128, 0, s2>>>(x);
    cudaEventRecord(ev_join, s2);

    // Binning path on the main (capture) stream
    k_zero_cnt<<<(N_NODES + 255) / 256, 256>>>();
    {
        int e4 = n_edges >> 2;
        int nt = e4 + (n_edges - e4 * 4);
        k_hist<<<(nt + 255) / 256, 256>>>(erow, n_edges);
    }
    k_scan1<<<N_CHUNKS, SCAN_CHUNK>>>();
    k_scan2<<<1, 256>>>();
    k_scan3<<<(N_NODES + 255) / 256, 256>>>(n_edges);
    k_place<<<(n_edges + 255) / 256, 256>>>(erow, ecol, eval, n_edges);

    // Join: rowgather needs both g_h (s2) and g_edge (main)
    cudaStreamWaitEvent(0, ev_join, 0);
    k_rowgather<<<(N_NODES + 3) / 4, 128>>>(out);
}

// round 6
// speedup vs baseline: 3.0784x; 1.0764x over previous
#include <cuda_runtime.h>
#include <cuda_bf16.h>
#include <cuda_fp16.h>

#define N_NODES 100000
#define DIM 128
#define MAX_EDGES 1700000
#define SCAN_CHUNK 512
#define N_CHUNKS ((N_NODES + SCAN_CHUNK - 1) / SCAN_CHUNK)   // 196

// ---------------------------------------------------------------------------
// Scratch (allocation-free rule: device globals)
// ---------------------------------------------------------------------------
__device__ __half g_h[N_NODES * DIM];         // h = x @ W^T  (fp16: halves gather bytes)
__device__ float  g_Wt[DIM * DIM];            // transposed W
__device__ int    g_cnt[N_NODES];
__device__ int    g_rowstart[N_NODES + 1];
__device__ int    g_cursor[N_NODES];
__device__ int    g_blocksum[N_CHUNKS];
__device__ int2   g_edge[MAX_EDGES];          // (col, val-bits) grouped by row

// ---------------------------------------------------------------------------
__global__ void k_prep_w(const float* __restrict__ W) {
    int idx = blockIdx.x * blockDim.x + threadIdx.x;
    if (idx >= DIM * DIM) return;
    int o = idx & 127;
    int k = idx >> 7;
    g_Wt[idx] = W[o * DIM + k];
}

// ---------------------------------------------------------------------------
// packed fp32x2 FMA (PTX-only on sm_103a)
// ---------------------------------------------------------------------------
__device__ __forceinline__ void ffma2(float2& d, float2 a, float2 b) {
    asm("fma.rn.f32x2 %0, %1, %2, %0;"
        : "+l"(*reinterpret_cast<unsigned long long*>(&d))
        : "l"(*reinterpret_cast<unsigned long long*>(&a)),
          "l"(*reinterpret_cast<unsigned long long*>(&b)));
}

// ---------------------------------------------------------------------------
// GEMM: h = x @ W^T, fp32x2 mainloop (proven), fp16 epilogue.
// ---------------------------------------------------------------------------
__global__ void __launch_bounds__(128) k_gemm(const float* __restrict__ x) {
    __shared__ float2 sxd[32 * DIM];
    const int tid  = threadIdx.x;
    const int op   = tid & 31;
    const int rg   = tid >> 5;
    const int row0 = blockIdx.x * 32;

    const float4* x4 = reinterpret_cast<const float4*>(x + (size_t)row0 * DIM);
    #pragma unroll
    for (int i = tid; i < 32 * 32; i += 128) {
        float4 v  = x4[i];
        int    r  = i >> 5;
        int    k4 = i & 31;
        float2* d = &sxd[r * DIM + k4 * 4];
        d[0] = make_float2(v.x, v.x);
        d[1] = make_float2(v.y, v.y);
        d[2] = make_float2(v.z, v.z);
        d[3] = make_float2(v.w, v.w);
    }
    __syncthreads();

    float2 acc[8][2];
    #pragma unroll
    for (int r = 0; r < 8; r++) {
        acc[r][0] = make_float2(0.f, 0.f);
        acc[r][1] = make_float2(0.f, 0.f);
    }

    const float2* sxr = &sxd[(rg * 8) * DIM];

    #pragma unroll 2
    for (int k = 0; k < DIM; k++) {
        float4 wv = *reinterpret_cast<const float4*>(&g_Wt[k * DIM + op * 4]);
        float2 wa = make_float2(wv.x, wv.y);
        float2 wb = make_float2(wv.z, wv.w);
        #pragma unroll
        for (int r = 0; r < 8; r++) {
            float2 xv = sxr[r * DIM + k];
            ffma2(acc[r][0], wa, xv);
            ffma2(acc[r][1], wb, xv);
        }
    }

    // Epilogue: convert to fp16, 8B store per row per thread (coalesced).
    __half* hp = g_h + (size_t)(row0 + rg * 8) * DIM + op * 4;
    #pragma unroll
    for (int r = 0; r < 8; r++) {
        __half2 p0 = __float22half2_rn(acc[r][0]);
        __half2 p1 = __float22half2_rn(acc[r][1]);
        uint2 st;
        st.x = *reinterpret_cast<unsigned*>(&p0);
        st.y = *reinterpret_cast<unsigned*>(&p1);
        *reinterpret_cast<uint2*>(hp + (size_t)r * DIM) = st;
    }
}

// ---------------------------------------------------------------------------
__global__ void k_zero_cnt() {
    int i = blockIdx.x * blockDim.x + threadIdx.x;
    if (i < N_NODES) g_cnt[i] = 0;
}

// Phase 1: histogram of rows (L2-atomic bound; leave as-is)
__global__ void k_hist(const int* __restrict__ erow, int n_edges) {
    int t  = blockIdx.x * blockDim.x + threadIdx.x;
    int e4 = n_edges >> 2;
    if (t < e4) {
        int4 r = reinterpret_cast<const int4*>(erow)[t];
        atomicAdd(&g_cnt[r.x], 1);
        atomicAdd(&g_cnt[r.y], 1);
        atomicAdd(&g_cnt[r.z], 1);
        atomicAdd(&g_cnt[r.w], 1);
    } else {
        int e = e4 * 4 + (t - e4);
        if (e < n_edges) atomicAdd(&g_cnt[erow[e]], 1);
    }
}

// ---------------------------------------------------------------------------
__global__ void __launch_bounds__(SCAN_CHUNK) k_scan1() {
    __shared__ int wsum[SCAN_CHUNK / 32];
    int tid  = threadIdx.x;
    int gidx = blockIdx.x * SCAN_CHUNK + tid;
    int v    = (gidx < N_NODES) ? g_cnt[gidx] : 0;

    int lane = tid & 31, wid = tid >> 5;
    int incl = v;
    #pragma unroll
    for (int d = 1; d < 32; d <<= 1) {
        int t = __shfl_up_sync(0xffffffff, incl, d);
        if (lane >= d) incl += t;
    }
    if (lane == 31) wsum[wid] = incl;
    __syncthreads();
    if (wid == 0) {
        int w = (lane < SCAN_CHUNK / 32) ? wsum[lane] : 0;
        int wi = w;
        #pragma unroll
        for (int d = 1; d < 32; d <<= 1) {
            int t = __shfl_up_sync(0xffffffff, wi, d);
            if (lane >= d) wi += t;
        }
        if (lane < SCAN_CHUNK / 32) wsum[lane] = wi - w;
    }
    __syncthreads();
    int excl = incl - v + wsum[wid];
    if (gidx < N_NODES) g_cnt[gidx] = excl;
    if (tid == SCAN_CHUNK - 1) g_blocksum[blockIdx.x] = excl + v;
}

__global__ void __launch_bounds__(256) k_scan2() {
    __shared__ int wsum[8];
    int tid = threadIdx.x;
    int v   = (tid < N_CHUNKS) ? g_blocksum[tid] : 0;
    int lane = tid & 31, wid = tid >> 5;
    int incl = v;
    #pragma unroll
    for (int d = 1; d < 32; d <<= 1) {
        int t = __shfl_up_sync(0xffffffff, incl, d);
        if (lane >= d) incl += t;
    }
    if (lane == 31) wsum[wid] = incl;
    __syncthreads();
    if (wid == 0) {
        int w = (lane < 8) ? wsum[lane] : 0;
        int wi = w;
        #pragma unroll
        for (int d = 1; d < 32; d <<= 1) {
            int t = __shfl_up_sync(0xffffffff, wi, d);
            if (lane >= d) wi += t;
        }
        if (lane < 8) wsum[lane] = wi - w;
    }
    __syncthreads();
    if (tid < N_CHUNKS) g_blocksum[tid] = incl - v + wsum[wid];
}

__global__ void k_scan3(int n_edges) {
    int i = blockIdx.x * blockDim.x + threadIdx.x;
    if (i < N_NODES) {
        int rs = g_cnt[i] + g_blocksum[i / SCAN_CHUNK];
        g_rowstart[i] = rs;
        g_cursor[i]   = rs;
    }
    if (i == 0) g_rowstart[N_NODES] = n_edges;
}

__global__ void k_place(const int*   __restrict__ erow,
                        const int*   __restrict__ ecol,
                        const float* __restrict__ eval,
                        int n_edges) {
    int e = blockIdx.x * blockDim.x + threadIdx.x;
    if (e >= n_edges) return;
    int r   = erow[e];
    int pos = atomicAdd(&g_cursor[r], 1);
    g_edge[pos] = make_int2(ecol[e], __float_as_int(eval[e]));
}

// ---------------------------------------------------------------------------
// Phase 4: one warp per output row; fp16 gather (8B/lane), MLP=8,
// fp32 accumulate, single coalesced float4 store.
// ---------------------------------------------------------------------------
__device__ __forceinline__ void acc_edge(float4& a, uint2 p, float v) {
    __half2 h01 = *reinterpret_cast<__half2*>(&p.x);
    __half2 h23 = *reinterpret_cast<__half2*>(&p.y);
    float2 f01 = __half22float2(h01);
    float2 f23 = __half22float2(h23);
    a.x += v * f01.x; a.y += v * f01.y;
    a.z += v * f23.x; a.w += v * f23.y;
}

__global__ void __launch_bounds__(128) k_rowgather(float* __restrict__ out) {
    int warp = blockIdx.x * 4 + (threadIdx.x >> 5);
    int lane = threadIdx.x & 31;
    if (warp >= N_NODES) return;

    int beg = __ldg(&g_rowstart[warp]);
    int end = __ldg(&g_rowstart[warp + 1]);

    const uint2* hh = reinterpret_cast<const uint2*>(g_h);   // 32 chunks of 8B per row

    float4 a0 = make_float4(0.f, 0.f, 0.f, 0.f);
    float4 a1 = make_float4(0.f, 0.f, 0.f, 0.f);
    float4 a2 = make_float4(0.f, 0.f, 0.f, 0.f);
    float4 a3 = make_float4(0.f, 0.f, 0.f, 0.f);

    int i = beg;
    for (; i + 8 <= end; i += 8) {
        int2 e0 = g_edge[i + 0];
        int2 e1 = g_edge[i + 1];
        int2 e2 = g_edge[i + 2];
        int2 e3 = g_edge[i + 3];
        int2 e4 = g_edge[i + 4];
        int2 e5 = g_edge[i + 5];
        int2 e6 = g_edge[i + 6];
        int2 e7 = g_edge[i + 7];
        uint2 p0 = hh[(size_t)e0.x * 32 + lane];
        uint2 p1 = hh[(size_t)e1.x * 32 + lane];
        uint2 p2 = hh[(size_t)e2.x * 32 + lane];
        uint2 p3 = hh[(size_t)e3.x * 32 + lane];
        uint2 p4 = hh[(size_t)e4.x * 32 + lane];
        uint2 p5 = hh[(size_t)e5.x * 32 + lane];
        uint2 p6 = hh[(size_t)e6.x * 32 + lane];
        uint2 p7 = hh[(size_t)e7.x * 32 + lane];
        acc_edge(a0, p0, __int_as_float(e0.y));
        acc_edge(a1, p1, __int_as_float(e1.y));
        acc_edge(a2, p2, __int_as_float(e2.y));
        acc_edge(a3, p3, __int_as_float(e3.y));
        acc_edge(a0, p4, __int_as_float(e4.y));
        acc_edge(a1, p5, __int_as_float(e5.y));
        acc_edge(a2, p6, __int_as_float(e6.y));
        acc_edge(a3, p7, __int_as_float(e7.y));
    }
    for (; i + 4 <= end; i += 4) {
        int2 e0 = g_edge[i + 0];
        int2 e1 = g_edge[i + 1];
        int2 e2 = g_edge[i + 2];
        int2 e3 = g_edge[i + 3];
        uint2 p0 = hh[(size_t)e0.x * 32 + lane];
        uint2 p1 = hh[(size_t)e1.x * 32 + lane];
        uint2 p2 = hh[(size_t)e2.x * 32 + lane];
        uint2 p3 = hh[(size_t)e3.x * 32 + lane];
        acc_edge(a0, p0, __int_as_float(e0.y));
        acc_edge(a1, p1, __int_as_float(e1.y));
        acc_edge(a2, p2, __int_as_float(e2.y));
        acc_edge(a3, p3, __int_as_float(e3.y));
    }
    for (; i < end; i++) {
        int2 e0 = g_edge[i];
        uint2 p0 = hh[(size_t)e0.x * 32 + lane];
        acc_edge(a0, p0, __int_as_float(e0.y));
    }

    float4 acc = make_float4(a0.x + a1.x + a2.x + a3.x,
                             a0.y + a1.y + a2.y + a3.y,
                             a0.z + a1.z + a2.z + a3.z,
                             a0.w + a1.w + a2.w + a3.w);
    *reinterpret_cast<float4*>(out + (size_t)warp * DIM + lane * 4) = acc;
}

// ---------------------------------------------------------------------------
extern "C" void kernel_launch(void* const* d_in, const int* in_sizes, int n_in,
                              void* d_out, int out_size) {
    const float* x    = (const float*)d_in[0];
    const float* W    = (const float*)d_in[1];
    const int*   erow = (const int*)  d_in[2];
    const int*   ecol = (const int*)  d_in[3];
    const float* eval = (const float*)d_in[4];
    float*       out  = (float*)d_out;

    int n_nodes = in_sizes[0] / DIM;
    int n_edges = in_sizes[2];

    static cudaStream_t s2 = nullptr;
    static cudaEvent_t  ev_fork = nullptr, ev_join = nullptr;
    if (!s2) {
        cudaStreamCreate(&s2);
        cudaEventCreateWithFlags(&ev_fork, cudaEventDisableTiming);
        cudaEventCreateWithFlags(&ev_join, cudaEventDisableTiming);
    }

    // Fork: GEMM path on s2
    cudaEventRecord(ev_fork, 0);
    cudaStreamWaitEvent(s2, ev_fork, 0);
    k_prep_w<<<(DIM * DIM + 255) / 256, 256, 0, s2>>>(W);
    k_gemm<<<(n_nodes + 31) / 32, 128, 0, s2>>>(x);
    cudaEventRecord(ev_join, s2);

    // Binning path on the main (capture) stream
    k_zero_cnt<<<(N_NODES + 255) / 256, 256>>>();
    {
        int e4 = n_edges >> 2;
        int nt = e4 + (n_edges - e4 * 4);
        k_hist<<<(nt + 255) / 256, 256>>>(erow, n_edges);
    }
    k_scan1<<<N_CHUNKS, SCAN_CHUNK>>>();
    k_scan2<<<1, 256>>>();
    k_scan3<<<(N_NODES + 255) / 256, 256>>>(n_edges);
    k_place<<<(n_edges + 255) / 256, 256>>>(erow, ecol, eval, n_edges);

    // Join: rowgather needs both g_h (s2) and g_edge (main)
    cudaStreamWaitEvent(0, ev_join, 0);
    k_rowgather<<<(N_NODES + 3) / 4, 128>>>(out);
}

// round 7
// speedup vs baseline: 4.2437x; 1.3785x over previous
#include <cuda_runtime.h>
#include <cuda_bf16.h>
#include <cuda_fp16.h>

#define N_NODES 100000
#define DIM 128
#define MAX_EDGES 1700000
#define SCAN_CHUNK 512
#define N_CHUNKS ((N_NODES + SCAN_CHUNK - 1) / SCAN_CHUNK)   // 196

// ---------------------------------------------------------------------------
// Scratch (allocation-free rule: device globals)
// ---------------------------------------------------------------------------
__device__ __half g_h[N_NODES * DIM];         // h = x @ W^T  (fp16)
__device__ __half g_Wh[DIM * DIM];            // W in fp16, identity layout [o][k]
__device__ int    g_cnt[N_NODES];
__device__ int    g_rowstart[N_NODES + 1];
__device__ int    g_cursor[N_NODES];
__device__ int    g_blocksum[N_CHUNKS];
__device__ int2   g_edge[MAX_EDGES];          // (col, val-bits) grouped by row

// ---------------------------------------------------------------------------
// Prep: W fp32 -> fp16 (same layout; mma B operand is col-major K x N, and
// B[k][n] = W[n][k], i.e. contiguous in k per n — exactly W's row layout).
// ---------------------------------------------------------------------------
__global__ void k_prep_w(const float* __restrict__ W) {
    int idx = blockIdx.x * blockDim.x + threadIdx.x;
    if (idx < DIM * DIM) g_Wh[idx] = __float2half_rn(W[idx]);
}

// ---------------------------------------------------------------------------
// GEMM via HMMA: h = x @ W^T, fp16 inputs, fp32 accum, fp16 output.
// Block = 256 threads (8 warps), 32 rows x 128 cols per block.
// Warp tile: 16 rows x 32 cols  (warp&1 -> row half, warp>>1 -> col quarter).
// smem rows padded to 136 halves: frag-load bank index = (4*qr + qc) mod 32,
// all 32 lanes distinct -> conflict-free.
// ---------------------------------------------------------------------------
#define SSTRIDE 136

__global__ void __launch_bounds__(256) k_gemm(const float* __restrict__ x) {
    __shared__ __half sA[32 * SSTRIDE];        // x tile fp16
    __shared__ __half sB[DIM * SSTRIDE];       // W fp16

    const int tid  = threadIdx.x;
    const int row0 = blockIdx.x * 32;

    // Load W (16384 halves = 2048 uint4), row-padded stores (16B aligned: 272%16==0)
    const uint4* w4 = reinterpret_cast<const uint4*>(g_Wh);
    #pragma unroll
    for (int i = tid; i < 2048; i += 256) {
        int r = i >> 4, cg = i & 15;
        *reinterpret_cast<uint4*>(&sB[r * SSTRIDE + cg * 8]) = w4[i];
    }
    // Load 32 x rows (1024 float4), convert fp32->fp16
    const float4* x4 = reinterpret_cast<const float4*>(x + (size_t)row0 * DIM);
    #pragma unroll
    for (int i = tid; i < 1024; i += 256) {
        float4 v = x4[i];
        int r = i >> 5, k4 = i & 31;
        __half2 p0 = __floats2half2_rn(v.x, v.y);
        __half2 p1 = __floats2half2_rn(v.z, v.w);
        __half* d = &sA[r * SSTRIDE + k4 * 4];
        *reinterpret_cast<__half2*>(d)     = p0;
        *reinterpret_cast<__half2*>(d + 2) = p1;
    }
    __syncthreads();

    const int warp = tid >> 5, lane = tid & 31;
    const int wr = (warp & 1) * 16;        // row tile base within block
    const int wc = (warp >> 1) * 32;       // col tile base
    const int qr = lane >> 2, qc = lane & 3;

    float c[4][4];
    #pragma unroll
    for (int nc = 0; nc < 4; nc++)
        #pragma unroll
        for (int j = 0; j < 4; j++) c[nc][j] = 0.f;

    #pragma unroll
    for (int ks = 0; ks < 8; ks++) {
        const int k0 = ks * 16 + qc * 2;
        const __half* A0 = &sA[(wr + qr) * SSTRIDE + k0];
        const __half* A8 = A0 + 8 * SSTRIDE;
        unsigned a0 = *reinterpret_cast<const unsigned*>(A0);
        unsigned a1 = *reinterpret_cast<const unsigned*>(A8);
        unsigned a2 = *reinterpret_cast<const unsigned*>(A0 + 8);
        unsigned a3 = *reinterpret_cast<const unsigned*>(A8 + 8);
        #pragma unroll
        for (int nc = 0; nc < 4; nc++) {
            const int n = wc + nc * 8 + qr;
            const __half* B0 = &sB[n * SSTRIDE + k0];
            unsigned b0 = *reinterpret_cast<const unsigned*>(B0);
            unsigned b1 = *reinterpret_cast<const unsigned*>(B0 + 8);
            asm("mma.sync.aligned.m16n8k16.row.col.f32.f16.f16.f32 "
                "{%0,%1,%2,%3}, {%4,%5,%6,%7}, {%8,%9}, {%0,%1,%2,%3};"
                : "+f"(c[nc][0]), "+f"(c[nc][1]), "+f"(c[nc][2]), "+f"(c[nc][3])
                : "r"(a0), "r"(a1), "r"(a2), "r"(a3), "r"(b0), "r"(b1));
        }
    }

    // Epilogue: fp16 stores. c0,c1 -> row g, cols t*2,t*2+1; c2,c3 -> row g+8.
    const int r0g = row0 + wr + qr;
    #pragma unroll
    for (int nc = 0; nc < 4; nc++) {
        const int col = wc + nc * 8 + qc * 2;
        __half2 lo = __floats2half2_rn(c[nc][0], c[nc][1]);
        __half2 hi = __floats2half2_rn(c[nc][2], c[nc][3]);
        *reinterpret_cast<__half2*>(&g_h[(size_t)r0g * DIM + col])       = lo;
        *reinterpret_cast<__half2*>(&g_h[(size_t)(r0g + 8) * DIM + col]) = hi;
    }
}

// ---------------------------------------------------------------------------
__global__ void k_zero_cnt() {
    int i = blockIdx.x * blockDim.x + threadIdx.x;
    if (i < N_NODES) g_cnt[i] = 0;
}

// Phase 1: histogram of rows (L2-atomic bound; proven — leave as-is)
__global__ void k_hist(const int* __restrict__ erow, int n_edges) {
    int t  = blockIdx.x * blockDim.x + threadIdx.x;
    int e4 = n_edges >> 2;
    if (t < e4) {
        int4 r = reinterpret_cast<const int4*>(erow)[t];
        atomicAdd(&g_cnt[r.x], 1);
        atomicAdd(&g_cnt[r.y], 1);
        atomicAdd(&g_cnt[r.z], 1);
        atomicAdd(&g_cnt[r.w], 1);
    } else {
        int e = e4 * 4 + (t - e4);
        if (e < n_edges) atomicAdd(&g_cnt[erow[e]], 1);
    }
}

// ---------------------------------------------------------------------------
__global__ void __launch_bounds__(SCAN_CHUNK) k_scan1() {
    __shared__ int wsum[SCAN_CHUNK / 32];
    int tid  = threadIdx.x;
    int gidx = blockIdx.x * SCAN_CHUNK + tid;
    int v    = (gidx < N_NODES) ? g_cnt[gidx] : 0;

    int lane = tid & 31, wid = tid >> 5;
    int incl = v;
    #pragma unroll
    for (int d = 1; d < 32; d <<= 1) {
        int t = __shfl_up_sync(0xffffffff, incl, d);
        if (lane >= d) incl += t;
    }
    if (lane == 31) wsum[wid] = incl;
    __syncthreads();
    if (wid == 0) {
        int w = (lane < SCAN_CHUNK / 32) ? wsum[lane] : 0;
        int wi = w;
        #pragma unroll
        for (int d = 1; d < 32; d <<= 1) {
            int t = __shfl_up_sync(0xffffffff, wi, d);
            if (lane >= d) wi += t;
        }
        if (lane < SCAN_CHUNK / 32) wsum[lane] = wi - w;
    }
    __syncthreads();
    int excl = incl - v + wsum[wid];
    if (gidx < N_NODES) g_cnt[gidx] = excl;
    if (tid == SCAN_CHUNK - 1) g_blocksum[blockIdx.x] = excl + v;
}

__global__ void __launch_bounds__(256) k_scan2() {
    __shared__ int wsum[8];
    int tid = threadIdx.x;
    int v   = (tid < N_CHUNKS) ? g_blocksum[tid] : 0;
    int lane = tid & 31, wid = tid >> 5;
    int incl = v;
    #pragma unroll
    for (int d = 1; d < 32; d <<= 1) {
        int t = __shfl_up_sync(0xffffffff, incl, d);
        if (lane >= d) incl += t;
    }
    if (lane == 31) wsum[wid] = incl;
    __syncthreads();
    if (wid == 0) {
        int w = (lane < 8) ? wsum[lane] : 0;
        int wi = w;
        #pragma unroll
        for (int d = 1; d < 32; d <<= 1) {
            int t = __shfl_up_sync(0xffffffff, wi, d);
            if (lane >= d) wi += t;
        }
        if (lane < 8) wsum[lane] = wi - w;
    }
    __syncthreads();
    if (tid < N_CHUNKS) g_blocksum[tid] = incl - v + wsum[wid];
}

__global__ void k_scan3(int n_edges) {
    int i = blockIdx.x * blockDim.x + threadIdx.x;
    if (i < N_NODES) {
        int rs = g_cnt[i] + g_blocksum[i / SCAN_CHUNK];
        g_rowstart[i] = rs;
        g_cursor[i]   = rs;
    }
    if (i == 0) g_rowstart[N_NODES] = n_edges;
}

__global__ void k_place(const int*   __restrict__ erow,
                        const int*   __restrict__ ecol,
                        const float* __restrict__ eval,
                        int n_edges) {
    int e = blockIdx.x * blockDim.x + threadIdx.x;
    if (e >= n_edges) return;
    int r   = erow[e];
    int pos = atomicAdd(&g_cursor[r], 1);
    g_edge[pos] = make_int2(ecol[e], __float_as_int(eval[e]));
}

// ---------------------------------------------------------------------------
// Phase 4: one warp per output row; fp16 gather (8B/lane), MLP=8,
// fp32 accumulate, single coalesced float4 store.  (unchanged — proven)
// ---------------------------------------------------------------------------
__device__ __forceinline__ void acc_edge(float4& a, uint2 p, float v) {
    __half2 h01 = *reinterpret_cast<__half2*>(&p.x);
    __half2 h23 = *reinterpret_cast<__half2*>(&p.y);
    float2 f01 = __half22float2(h01);
    float2 f23 = __half22float2(h23);
    a.x += v * f01.x; a.y += v * f01.y;
    a.z += v * f23.x; a.w += v * f23.y;
}

__global__ void __launch_bounds__(128) k_rowgather(float* __restrict__ out) {
    int warp = blockIdx.x * 4 + (threadIdx.x >> 5);
    int lane = threadIdx.x & 31;
    if (warp >= N_NODES) return;

    int beg = __ldg(&g_rowstart[warp]);
    int end = __ldg(&g_rowstart[warp + 1]);

    const uint2* hh = reinterpret_cast<const uint2*>(g_h);

    float4 a0 = make_float4(0.f, 0.f, 0.f, 0.f);
    float4 a1 = make_float4(0.f, 0.f, 0.f, 0.f);
    float4 a2 = make_float4(0.f, 0.f, 0.f, 0.f);
    float4 a3 = make_float4(0.f, 0.f, 0.f, 0.f);

    int i = beg;
    for (; i + 8 <= end; i += 8) {
        int2 e0 = g_edge[i + 0];
        int2 e1 = g_edge[i + 1];
        int2 e2 = g_edge[i + 2];
        int2 e3 = g_edge[i + 3];
        int2 e4 = g_edge[i + 4];
        int2 e5 = g_edge[i + 5];
        int2 e6 = g_edge[i + 6];
        int2 e7 = g_edge[i + 7];
        uint2 p0 = hh[(size_t)e0.x * 32 + lane];
        uint2 p1 = hh[(size_t)e1.x * 32 + lane];
        uint2 p2 = hh[(size_t)e2.x * 32 + lane];
        uint2 p3 = hh[(size_t)e3.x * 32 + lane];
        uint2 p4 = hh[(size_t)e4.x * 32 + lane];
        uint2 p5 = hh[(size_t)e5.x * 32 + lane];
        uint2 p6 = hh[(size_t)e6.x * 32 + lane];
        uint2 p7 = hh[(size_t)e7.x * 32 + lane];
        acc_edge(a0, p0, __int_as_float(e0.y));
        acc_edge(a1, p1, __int_as_float(e1.y));
        acc_edge(a2, p2, __int_as_float(e2.y));
        acc_edge(a3, p3, __int_as_float(e3.y));
        acc_edge(a0, p4, __int_as_float(e4.y));
        acc_edge(a1, p5, __int_as_float(e5.y));
        acc_edge(a2, p6, __int_as_float(e6.y));
        acc_edge(a3, p7, __int_as_float(e7.y));
    }
    for (; i + 4 <= end; i += 4) {
        int2 e0 = g_edge[i + 0];
        int2 e1 = g_edge[i + 1];
        int2 e2 = g_edge[i + 2];
        int2 e3 = g_edge[i + 3];
        uint2 p0 = hh[(size_t)e0.x * 32 + lane];
        uint2 p1 = hh[(size_t)e1.x * 32 + lane];
        uint2 p2 = hh[(size_t)e2.x * 32 + lane];
        uint2 p3 = hh[(size_t)e3.x * 32 + lane];
        acc_edge(a0, p0, __int_as_float(e0.y));
        acc_edge(a1, p1, __int_as_float(e1.y));
        acc_edge(a2, p2, __int_as_float(e2.y));
        acc_edge(a3, p3, __int_as_float(e3.y));
    }
    for (; i < end; i++) {
        int2 e0 = g_edge[i];
        uint2 p0 = hh[(size_t)e0.x * 32 + lane];
        acc_edge(a0, p0, __int_as_float(e0.y));
    }

    float4 acc = make_float4(a0.x + a1.x + a2.x + a3.x,
                             a0.y + a1.y + a2.y + a3.y,
                             a0.z + a1.z + a2.z + a3.z,
                             a0.w + a1.w + a2.w + a3.w);
    *reinterpret_cast<float4*>(out + (size_t)warp * DIM + lane * 4) = acc;
}

// ---------------------------------------------------------------------------
extern "C" void kernel_launch(void* const* d_in, const int* in_sizes, int n_in,
                              void* d_out, int out_size) {
    const float* x    = (const float*)d_in[0];
    const float* W    = (const float*)d_in[1];
    const int*   erow = (const int*)  d_in[2];
    const int*   ecol = (const int*)  d_in[3];
    const float* eval = (const float*)d_in[4];
    float*       out  = (float*)d_out;

    int n_nodes = in_sizes[0] / DIM;
    int n_edges = in_sizes[2];

    static cudaStream_t s2 = nullptr;
    static cudaEvent_t  ev_fork = nullptr, ev_join = nullptr;
    if (!s2) {
        cudaStreamCreate(&s2);
        cudaEventCreateWithFlags(&ev_fork, cudaEventDisableTiming);
        cudaEventCreateWithFlags(&ev_join, cudaEventDisableTiming);
    }

    // Fork: GEMM path on s2
    cudaEventRecord(ev_fork, 0);
    cudaStreamWaitEvent(s2, ev_fork, 0);
    k_prep_w<<<(DIM * DIM + 255) / 256, 256, 0, s2>>>(W);
    k_gemm<<<(n_nodes + 31) / 32, 256, 0, s2>>>(x);
    cudaEventRecord(ev_join, s2);

    // Binning path on the main (capture) stream
    k_zero_cnt<<<(N_NODES + 255) / 256, 256>>>();
    {
        int e4 = n_edges >> 2;
        int nt = e4 + (n_edges - e4 * 4);
        k_hist<<<(nt + 255) / 256, 256>>>(erow, n_edges);
    }
    k_scan1<<<N_CHUNKS, SCAN_CHUNK>>>();
    k_scan2<<<1, 256>>>();
    k_scan3<<<(N_NODES + 255) / 256, 256>>>(n_edges);
    k_place<<<(n_edges + 255) / 256, 256>>>(erow, ecol, eval, n_edges);

    // Join: rowgather needs both g_h (s2) and g_edge (main)
    cudaStreamWaitEvent(0, ev_join, 0);
    k_rowgather<<<(N_NODES + 3) / 4, 128>>>(out);
}

// round 8
// speedup vs baseline: 4.4368x; 1.0455x over previous
#include <cuda_runtime.h>
#include <cuda_bf16.h>
#include <cuda_fp16.h>

#define N_NODES 100000
#define DIM 128
#define MAX_EDGES 1700000
#define SCAN_CHUNK 512
#define N_CHUNKS ((N_NODES + SCAN_CHUNK - 1) / SCAN_CHUNK)   // 196

// ---------------------------------------------------------------------------
// Scratch (allocation-free rule: device globals)
// ---------------------------------------------------------------------------
__device__ __half g_h[N_NODES * DIM];         // h = x @ W^T  (fp16)
__device__ __half g_Wh[DIM * DIM];            // W in fp16
__device__ int    g_cnt[N_NODES];
__device__ int    g_rowstart[N_NODES + 1];
__device__ int    g_cursor[N_NODES];
__device__ int    g_blocksum[N_CHUNKS];
__device__ int2   g_edge[MAX_EDGES];          // (col, val-bits) grouped by row

// ---------------------------------------------------------------------------
__global__ void k_prep_w(const float* __restrict__ W) {
    int idx = blockIdx.x * blockDim.x + threadIdx.x;
    if (idx < DIM * DIM) g_Wh[idx] = __float2half_rn(W[idx]);
}

// ---------------------------------------------------------------------------
// GEMM via HMMA (unchanged — proven ~15us, hidden under binning branch)
// ---------------------------------------------------------------------------
#define SSTRIDE 136

__global__ void __launch_bounds__(256) k_gemm(const float* __restrict__ x) {
    __shared__ __half sA[32 * SSTRIDE];
    __shared__ __half sB[DIM * SSTRIDE];

    const int tid  = threadIdx.x;
    const int row0 = blockIdx.x * 32;

    const uint4* w4 = reinterpret_cast<const uint4*>(g_Wh);
    #pragma unroll
    for (int i = tid; i < 2048; i += 256) {
        int r = i >> 4, cg = i & 15;
        *reinterpret_cast<uint4*>(&sB[r * SSTRIDE + cg * 8]) = w4[i];
    }
    const float4* x4 = reinterpret_cast<const float4*>(x + (size_t)row0 * DIM);
    #pragma unroll
    for (int i = tid; i < 1024; i += 256) {
        float4 v = x4[i];
        int r = i >> 5, k4 = i & 31;
        __half2 p0 = __floats2half2_rn(v.x, v.y);
        __half2 p1 = __floats2half2_rn(v.z, v.w);
        __half* d = &sA[r * SSTRIDE + k4 * 4];
        *reinterpret_cast<__half2*>(d)     = p0;
        *reinterpret_cast<__half2*>(d + 2) = p1;
    }
    __syncthreads();

    const int warp = tid >> 5, lane = tid & 31;
    const int wr = (warp & 1) * 16;
    const int wc = (warp >> 1) * 32;
    const int qr = lane >> 2, qc = lane & 3;

    float c[4][4];
    #pragma unroll
    for (int nc = 0; nc < 4; nc++)
        #pragma unroll
        for (int j = 0; j < 4; j++) c[nc][j] = 0.f;

    #pragma unroll
    for (int ks = 0; ks < 8; ks++) {
        const int k0 = ks * 16 + qc * 2;
        const __half* A0 = &sA[(wr + qr) * SSTRIDE + k0];
        const __half* A8 = A0 + 8 * SSTRIDE;
        unsigned a0 = *reinterpret_cast<const unsigned*>(A0);
        unsigned a1 = *reinterpret_cast<const unsigned*>(A8);
        unsigned a2 = *reinterpret_cast<const unsigned*>(A0 + 8);
        unsigned a3 = *reinterpret_cast<const unsigned*>(A8 + 8);
        #pragma unroll
        for (int nc = 0; nc < 4; nc++) {
            const int n = wc + nc * 8 + qr;
            const __half* B0 = &sB[n * SSTRIDE + k0];
            unsigned b0 = *reinterpret_cast<const unsigned*>(B0);
            unsigned b1 = *reinterpret_cast<const unsigned*>(B0 + 8);
            asm("mma.sync.aligned.m16n8k16.row.col.f32.f16.f16.f32 "
                "{%0,%1,%2,%3}, {%4,%5,%6,%7}, {%8,%9}, {%0,%1,%2,%3};"
                : "+f"(c[nc][0]), "+f"(c[nc][1]), "+f"(c[nc][2]), "+f"(c[nc][3])
                : "r"(a0), "r"(a1), "r"(a2), "r"(a3), "r"(b0), "r"(b1));
        }
    }

    const int r0g = row0 + wr + qr;
    #pragma unroll
    for (int nc = 0; nc < 4; nc++) {
        const int col = wc + nc * 8 + qc * 2;
        __half2 lo = __floats2half2_rn(c[nc][0], c[nc][1]);
        __half2 hi = __floats2half2_rn(c[nc][2], c[nc][3]);
        *reinterpret_cast<__half2*>(&g_h[(size_t)r0g * DIM + col])       = lo;
        *reinterpret_cast<__half2*>(&g_h[(size_t)(r0g + 8) * DIM + col]) = hi;
    }
}

// ---------------------------------------------------------------------------
__global__ void k_zero_cnt() {
    int i = blockIdx.x * blockDim.x + threadIdx.x;
    if (i < N_NODES) g_cnt[i] = 0;
}

// Phase 1: histogram of rows (L2-atomic bound; at floor — leave as-is)
__global__ void k_hist(const int* __restrict__ erow, int n_edges) {
    int t  = blockIdx.x * blockDim.x + threadIdx.x;
    int e4 = n_edges >> 2;
    if (t < e4) {
        int4 r = reinterpret_cast<const int4*>(erow)[t];
        atomicAdd(&g_cnt[r.x], 1);
        atomicAdd(&g_cnt[r.y], 1);
        atomicAdd(&g_cnt[r.z], 1);
        atomicAdd(&g_cnt[r.w], 1);
    } else {
        int e = e4 * 4 + (t - e4);
        if (e < n_edges) atomicAdd(&g_cnt[erow[e]], 1);
    }
}

// ---------------------------------------------------------------------------
__global__ void __launch_bounds__(SCAN_CHUNK) k_scan1() {
    __shared__ int wsum[SCAN_CHUNK / 32];
    int tid  = threadIdx.x;
    int gidx = blockIdx.x * SCAN_CHUNK + tid;
    int v    = (gidx < N_NODES) ? g_cnt[gidx] : 0;

    int lane = tid & 31, wid = tid >> 5;
    int incl = v;
    #pragma unroll
    for (int d = 1; d < 32; d <<= 1) {
        int t = __shfl_up_sync(0xffffffff, incl, d);
        if (lane >= d) incl += t;
    }
    if (lane == 31) wsum[wid] = incl;
    __syncthreads();
    if (wid == 0) {
        int w = (lane < SCAN_CHUNK / 32) ? wsum[lane] : 0;
        int wi = w;
        #pragma unroll
        for (int d = 1; d < 32; d <<= 1) {
            int t = __shfl_up_sync(0xffffffff, wi, d);
            if (lane >= d) wi += t;
        }
        if (lane < SCAN_CHUNK / 32) wsum[lane] = wi - w;
    }
    __syncthreads();
    int excl = incl - v + wsum[wid];
    if (gidx < N_NODES) g_cnt[gidx] = excl;
    if (tid == SCAN_CHUNK - 1) g_blocksum[blockIdx.x] = excl + v;
}

__global__ void __launch_bounds__(256) k_scan2() {
    __shared__ int wsum[8];
    int tid = threadIdx.x;
    int v   = (tid < N_CHUNKS) ? g_blocksum[tid] : 0;
    int lane = tid & 31, wid = tid >> 5;
    int incl = v;
    #pragma unroll
    for (int d = 1; d < 32; d <<= 1) {
        int t = __shfl_up_sync(0xffffffff, incl, d);
        if (lane >= d) incl += t;
    }
    if (lane == 31) wsum[wid] = incl;
    __syncthreads();
    if (wid == 0) {
        int w = (lane < 8) ? wsum[lane] : 0;
        int wi = w;
        #pragma unroll
        for (int d = 1; d < 32; d <<= 1) {
            int t = __shfl_up_sync(0xffffffff, wi, d);
            if (lane >= d) wi += t;
        }
        if (lane < 8) wsum[lane] = wi - w;
    }
    __syncthreads();
    if (tid < N_CHUNKS) g_blocksum[tid] = incl - v + wsum[wid];
}

__global__ void k_scan3(int n_edges) {
    int i = blockIdx.x * blockDim.x + threadIdx.x;
    if (i < N_NODES) {
        int rs = g_cnt[i] + g_blocksum[i / SCAN_CHUNK];
        g_rowstart[i] = rs;
        g_cursor[i]   = rs;
    }
    if (i == 0) g_rowstart[N_NODES] = n_edges;
}

// Phase 3: place — 4 edges per thread, vectorized loads
__global__ void k_place(const int*   __restrict__ erow,
                        const int*   __restrict__ ecol,
                        const float* __restrict__ eval,
                        int n_edges) {
    int t  = blockIdx.x * blockDim.x + threadIdx.x;
    int e4 = n_edges >> 2;
    if (t < e4) {
        int4   r = reinterpret_cast<const int4*>(erow)[t];
        int4   c = reinterpret_cast<const int4*>(ecol)[t];
        float4 v = reinterpret_cast<const float4*>(eval)[t];
        int p0 = atomicAdd(&g_cursor[r.x], 1);
        int p1 = atomicAdd(&g_cursor[r.y], 1);
        int p2 = atomicAdd(&g_cursor[r.z], 1);
        int p3 = atomicAdd(&g_cursor[r.w], 1);
        g_edge[p0] = make_int2(c.x, __float_as_int(v.x));
        g_edge[p1] = make_int2(c.y, __float_as_int(v.y));
        g_edge[p2] = make_int2(c.z, __float_as_int(v.z));
        g_edge[p3] = make_int2(c.w, __float_as_int(v.w));
    } else {
        int e = e4 * 4 + (t - e4);
        if (e < n_edges) {
            int pos = atomicAdd(&g_cursor[erow[e]], 1);
            g_edge[pos] = make_int2(ecol[e], __float_as_int(eval[e]));
        }
    }
}

// ---------------------------------------------------------------------------
// Phase 4: 16 lanes per output row (2 rows per warp). Each lane covers 8
// columns via one LDG.128 per edge: half the gather instructions of the
// 32-lane version, double the in-flight edges per warp. fp32 accumulate.
// ---------------------------------------------------------------------------
__device__ __forceinline__ void acc_edge16(float4& aLo, float4& aHi, uint4 p, float v) {
    float2 f0 = __half22float2(*reinterpret_cast<__half2*>(&p.x));
    float2 f1 = __half22float2(*reinterpret_cast<__half2*>(&p.y));
    float2 f2 = __half22float2(*reinterpret_cast<__half2*>(&p.z));
    float2 f3 = __half22float2(*reinterpret_cast<__half2*>(&p.w));
    aLo.x += v * f0.x; aLo.y += v * f0.y; aLo.z += v * f1.x; aLo.w += v * f1.y;
    aHi.x += v * f2.x; aHi.y += v * f2.y; aHi.z += v * f3.x; aHi.w += v * f3.y;
}

__global__ void __launch_bounds__(128) k_rowgather(float* __restrict__ out) {
    int grp = blockIdx.x * 8 + (threadIdx.x >> 4);   // 16-lane group = one row
    int sl  = threadIdx.x & 15;
    if (grp >= N_NODES) return;

    int beg = __ldg(&g_rowstart[grp]);
    int end = __ldg(&g_rowstart[grp + 1]);

    const uint4* hh = reinterpret_cast<const uint4*>(g_h);   // 16 x 16B per row

    float4 l0 = make_float4(0.f,0.f,0.f,0.f), h0 = make_float4(0.f,0.f,0.f,0.f);
    float4 l1 = make_float4(0.f,0.f,0.f,0.f), h1 = make_float4(0.f,0.f,0.f,0.f);

    int i = beg;
    for (; i + 8 <= end; i += 8) {
        int2 e0 = g_edge[i + 0];
        int2 e1 = g_edge[i + 1];
        int2 e2 = g_edge[i + 2];
        int2 e3 = g_edge[i + 3];
        int2 e4 = g_edge[i + 4];
        int2 e5 = g_edge[i + 5];
        int2 e6 = g_edge[i + 6];
        int2 e7 = g_edge[i + 7];
        uint4 p0 = hh[(size_t)e0.x * 16 + sl];
        uint4 p1 = hh[(size_t)e1.x * 16 + sl];
        uint4 p2 = hh[(size_t)e2.x * 16 + sl];
        uint4 p3 = hh[(size_t)e3.x * 16 + sl];
        uint4 p4 = hh[(size_t)e4.x * 16 + sl];
        uint4 p5 = hh[(size_t)e5.x * 16 + sl];
        uint4 p6 = hh[(size_t)e6.x * 16 + sl];
        uint4 p7 = hh[(size_t)e7.x * 16 + sl];
        acc_edge16(l0, h0, p0, __int_as_float(e0.y));
        acc_edge16(l1, h1, p1, __int_as_float(e1.y));
        acc_edge16(l0, h0, p2, __int_as_float(e2.y));
        acc_edge16(l1, h1, p3, __int_as_float(e3.y));
        acc_edge16(l0, h0, p4, __int_as_float(e4.y));
        acc_edge16(l1, h1, p5, __int_as_float(e5.y));
        acc_edge16(l0, h0, p6, __int_as_float(e6.y));
        acc_edge16(l1, h1, p7, __int_as_float(e7.y));
    }
    for (; i + 2 <= end; i += 2) {
        int2 e0 = g_edge[i + 0];
        int2 e1 = g_edge[i + 1];
        uint4 p0 = hh[(size_t)e0.x * 16 + sl];
        uint4 p1 = hh[(size_t)e1.x * 16 + sl];
        acc_edge16(l0, h0, p0, __int_as_float(e0.y));
        acc_edge16(l1, h1, p1, __int_as_float(e1.y));
    }
    if (i < end) {
        int2 e0 = g_edge[i];
        uint4 p0 = hh[(size_t)e0.x * 16 + sl];
        acc_edge16(l0, h0, p0, __int_as_float(e0.y));
    }

    float4 lo = make_float4(l0.x + l1.x, l0.y + l1.y, l0.z + l1.z, l0.w + l1.w);
    float4 hi = make_float4(h0.x + h1.x, h0.y + h1.y, h0.z + h1.z, h0.w + h1.w);

    float* op = out + (size_t)grp * DIM + sl * 8;
    *reinterpret_cast<float4*>(op)     = lo;
    *reinterpret_cast<float4*>(op + 4) = hi;
}

// ---------------------------------------------------------------------------
extern "C" void kernel_launch(void* const* d_in, const int* in_sizes, int n_in,
                              void* d_out, int out_size) {
    const float* x    = (const float*)d_in[0];
    const float* W    = (const float*)d_in[1];
    const int*   erow = (const int*)  d_in[2];
    const int*   ecol = (const int*)  d_in[3];
    const float* eval = (const float*)d_in[4];
    float*       out  = (float*)d_out;

    int n_nodes = in_sizes[0] / DIM;
    int n_edges = in_sizes[2];

    static cudaStream_t s2 = nullptr;
    static cudaEvent_t  ev_fork = nullptr, ev_join = nullptr;
    if (!s2) {
        cudaStreamCreate(&s2);
        cudaEventCreateWithFlags(&ev_fork, cudaEventDisableTiming);
        cudaEventCreateWithFlags(&ev_join, cudaEventDisableTiming);
    }

    // Fork: GEMM path on s2
    cudaEventRecord(ev_fork, 0);
    cudaStreamWaitEvent(s2, ev_fork, 0);
    k_prep_w<<<(DIM * DIM + 255) / 256, 256, 0, s2>>>(W);
    k_gemm<<<(n_nodes + 31) / 32, 256, 0, s2>>>(x);
    cudaEventRecord(ev_join, s2);

    // Binning path on the main (capture) stream
    k_zero_cnt<<<(N_NODES + 255) / 256, 256>>>();
    {
        int e4 = n_edges >> 2;
        int nt = e4 + (n_edges - e4 * 4);
        k_hist<<<(nt + 255) / 256, 256>>>(erow, n_edges);
    }
    k_scan1<<<N_CHUNKS, SCAN_CHUNK>>>();
    k_scan2<<<1, 256>>>();
    k_scan3<<<(N_NODES + 255) / 256, 256>>>(n_edges);
    {
        int e4 = n_edges >> 2;
        int nt = e4 + (n_edges - e4 * 4);
        k_place<<<(nt + 255) / 256, 256>>>(erow, ecol, eval, n_edges);
    }

    // Join: rowgather needs both g_h (s2) and g_edge (main)
    cudaStreamWaitEvent(0, ev_join, 0);
    k_rowgather<<<(N_NODES + 7) / 8, 128>>>(out);
}